// round 15
// baseline (speedup 1.0000x reference)
#include <cuda_runtime.h>
#include <cuda_fp16.h>
#include <math.h>
#include <stdint.h>

// Problem constants (B = D_IN = S = 1024)
#define NB 1024
#define NS 1024
#define NSTEPS 15   // TIME_LIMIT - 1
#define NUNF 3      // ODE_UNFOLDS

// ---------------------------------------------------------------------------
// Scratch (device globals; no allocations allowed)
// ---------------------------------------------------------------------------
__device__ __align__(16) float g_X  [NB * NS];     // inputs @ Wx + b
__device__ __align__(16) float g_hf0[NB * NS];     // fp32 hidden ping-pong
__device__ __align__(16) float g_hf1[NB * NS];
__device__ __align__(16) __half g_hhi0[NB * NS];   // fp16 hidden ping-pong
__device__ __align__(16) __half g_hhi1[NB * NS];
__device__ __align__(16) __half g_WhT_hi[NS * NS];   // Wh^T split
__device__ __align__(16) __half g_WhT_lo[NS * NS];
__device__ __align__(16) __half g_WxT_hi[NS * NS];   // Wx^T split
__device__ __align__(16) __half g_WxT_lo[NS * NS];
__device__ __align__(16) __half g_inhi[NB * NS];     // inputs (fp16)
__device__ float g_haltacc[NB];   // halt_acc == tot_rem
__device__ float g_steps[NB];
__device__ int   g_cont[NB];

// ---------------------------------------------------------------------------
// Warp-level tensor-core helpers (sm_80+ PTX; assembles for plain sm_100)
// ---------------------------------------------------------------------------
__device__ __forceinline__ uint32_t smem_u32(const void* p) {
    uint32_t a;
    asm("{ .reg .u64 t; cvta.to.shared.u64 t, %1; cvt.u32.u64 %0, t; }"
        : "=r"(a) : "l"(p));
    return a;
}

__device__ __forceinline__ void ldm_x4(uint32_t* r, uint32_t addr) {
    asm volatile("ldmatrix.sync.aligned.m8n8.x4.shared.b16 {%0,%1,%2,%3}, [%4];"
        : "=r"(r[0]), "=r"(r[1]), "=r"(r[2]), "=r"(r[3]) : "r"(addr));
}
// fp16 operands, fp32 accumulate
__device__ __forceinline__ void mma_f32acc(float* c, const uint32_t* a,
                                           const uint32_t* b) {
    asm volatile(
        "mma.sync.aligned.m16n8k16.row.col.f32.f16.f16.f32 "
        "{%0,%1,%2,%3}, {%4,%5,%6,%7}, {%8,%9}, {%0,%1,%2,%3};"
        : "+f"(c[0]), "+f"(c[1]), "+f"(c[2]), "+f"(c[3])
        : "r"(a[0]), "r"(a[1]), "r"(a[2]), "r"(a[3]), "r"(b[0]), "r"(b[1]));
}
__device__ __forceinline__ void cp16(uint32_t saddr, const void* g) {
    asm volatile("cp.async.cg.shared.global [%0], [%1], 16;"
                 :: "r"(saddr), "l"(g));
}

// ---------------------------------------------------------------------------
// Prep kernels (exactly 3 launches so gemm_tc lands in the ncu window)
// ---------------------------------------------------------------------------
__global__ __launch_bounds__(256) void init_kernel(float* __restrict__ tot_h) {
    int i = blockIdx.x * blockDim.x + threadIdx.x;
    int stride = gridDim.x * blockDim.x;
    for (int j = i; j < NB * NS; j += stride) tot_h[j] = 0.0f;
    if (i < NB) { g_haltacc[i] = 0.0f; g_steps[i] = 0.0f; g_cont[i] = 1; }
}

// Both weight transposes in one launch: blocks 0-1023 Wx, 1024-2047 Wh.
__global__ __launch_bounds__(256) void transpose_both(
    const float* __restrict__ Wx, const float* __restrict__ Wh,
    __half* __restrict__ WxThi, __half* __restrict__ WxTlo,
    __half* __restrict__ WhThi, __half* __restrict__ WhTlo)
{
    const int which = blockIdx.x >> 10;
    const int t = blockIdx.x & 1023;
    const float* W = which ? Wh : Wx;
    __half* Thi = which ? WhThi : WxThi;
    __half* Tlo = which ? WhTlo : WxTlo;

    __shared__ float tb[32][33];
    const int x  = threadIdx.x & 31;
    const int y0 = threadIdx.x >> 5;    // 0..7
    const int bk = (t >> 5) * 32;       // W row (k) block
    const int bn = (t & 31) * 32;       // W col (n) block
#pragma unroll
    for (int i = 0; i < 32; i += 8)
        tb[y0 + i][x] = W[(size_t)(bk + y0 + i) * NS + bn + x];
    __syncthreads();
#pragma unroll
    for (int i = 0; i < 32; i += 8) {
        float v = tb[x][y0 + i];  // = W[bk+x][bn+y0+i]
        size_t o = (size_t)(bn + y0 + i) * NS + bk + x;
        __half h = __float2half(v);
        Thi[o] = h;
        Tlo[o] = __float2half(v - __half2float(h));
    }
}

// Both fp16 casts in one launch: blocks 0-4095 inputs, 4096-8191 hidden0.
__global__ __launch_bounds__(256) void cast_both(
    const float* __restrict__ inputs, const float* __restrict__ hidden0,
    __half* __restrict__ ihi, __half* __restrict__ hhi)
{
    const int which = blockIdx.x >> 12;
    const int i = ((blockIdx.x & 4095) << 8) + threadIdx.x;
    const float* src = which ? hidden0 : inputs;
    __half* hi = which ? hhi : ihi;
    hi[i] = __float2half(src[i]);
}

// ---------------------------------------------------------------------------
// Tensor-core GEMM (2-product fp16) + fused LTC epilogue.
//   C = Ah.Bh + Ah.Bl   (fp32 acc; dropped A_lo.B ~ 1.2e-4 on z)
// CTA tile 128(m) x 64(n), 8 warps of 32x32 (fat warp tiles cut LDSM
// traffic to 0.375 x4-ops/MMA), 256 threads, grid 128 CTAs = one wave.
// K-chunks of 64, 3-stage cp.async pipeline, ONE __syncthreads per chunk,
// XOR-swizzled smem, frag double-buffer across ks.
//   mode 0: out_f = C + bias[col]
//   mode 1: z = C + X; f = sigmoid(z);
//           h' = (h_old + dt f A)/(1 + dt(1/tau + f))
//           out_f = h' fp32; out_hi = fp16(h')
// ---------------------------------------------------------------------------
#define AH_OFF 0
#define BH_OFF 16384
#define BL_OFF 24576
#define STAGE_BYTES 32768
#define GEMM_SMEM (3 * STAGE_BYTES)   // 98304

__global__ __launch_bounds__(256, 1) void gemm_tc(
    const __half* __restrict__ Ahi,
    const __half* __restrict__ Bhi, const __half* __restrict__ Blo,
    const float* __restrict__ Xb,      // mode0: bias[S]; mode1: X [B x S]
    const float* __restrict__ h_old,   // mode1
    const float* __restrict__ Avec, const float* __restrict__ tauv,
    float* __restrict__ out_f,
    __half* __restrict__ out_hi,
    int mode)
{
    extern __shared__ char smem[];
    const uint32_t sb = smem_u32(smem);

    const int tid = threadIdx.x;
    const int wid = tid >> 5, lid = tid & 31;
    const int warpM = wid >> 1;       // 0..3 -> m32 tile
    const int warpN = wid & 1;        // 0..1 -> n32 tile
    const int rowBase = blockIdx.y * 128;
    const int colBase = blockIdx.x * 64;

    // ldmatrix offsets (stage-relative).
    const int laneAr = lid & 15, laneAk = lid >> 4;
    uint32_t offA[2][4], offB[2][4];
#pragma unroll
    for (int mi = 0; mi < 2; mi++) {
        const int rowA = warpM * 32 + mi * 16 + laneAr;
#pragma unroll
        for (int ks = 0; ks < 4; ks++)
            offA[mi][ks] = (uint32_t)(AH_OFF + rowA * 128 +
                ((ks * 32 + laneAk * 16) ^ ((rowA & 7) << 4)));
    }
    const int laneBt = lid >> 3;      // tile id 0..3
#pragma unroll
    for (int pr = 0; pr < 2; pr++) {
        const int rowB = warpN * 32 + pr * 16 + (laneBt >> 1) * 8 + (lid & 7);
#pragma unroll
        for (int ks = 0; ks < 4; ks++)
            offB[pr][ks] = (uint32_t)(BH_OFF + rowB * 128 +
                ((ks * 32 + (laneBt & 1) * 16) ^ ((rowB & 7) << 4)));
    }

    float acc[2][4][4];
#pragma unroll
    for (int mi = 0; mi < 2; mi++)
#pragma unroll
        for (int ni = 0; ni < 4; ni++)
#pragma unroll
            for (int j = 0; j < 4; j++) acc[mi][ni][j] = 0.0f;

    const char* ahg = (const char*)Ahi + (size_t)rowBase * 2048;
    const char* bhg = (const char*)Bhi + (size_t)colBase * 2048;
    const char* blg = (const char*)Blo + (size_t)colBase * 2048;

    auto issue_load = [&](int cc) {
        const int kb = cc * 128;      // byte offset along K
        const uint32_t buf = sb + (uint32_t)(cc % 3) * STAGE_BYTES;
#pragma unroll
        for (int i = 0; i < 4; i++) {            // A: 128 rows x 8 segs
            int idx = i * 256 + tid;
            int row = idx >> 3, s = idx & 7;
            uint32_t off = (uint32_t)(row * 128 + ((s * 16) ^ ((row & 7) << 4)));
            cp16(buf + AH_OFF + off, ahg + (size_t)row * 2048 + kb + s * 16);
        }
#pragma unroll
        for (int i = 0; i < 2; i++) {            // B: 64 rows x 8 segs, hi+lo
            int idx = i * 256 + tid;
            int row = idx >> 3, s = idx & 7;
            uint32_t off = (uint32_t)(row * 128 + ((s * 16) ^ ((row & 7) << 4)));
            const size_t g = (size_t)row * 2048 + kb + s * 16;
            cp16(buf + BH_OFF + off, bhg + g);
            cp16(buf + BL_OFF + off, blg + g);
        }
        asm volatile("cp.async.commit_group;" ::: "memory");
    };

    issue_load(0);
    issue_load(1);

    // double-buffered fragments, pipelined across ks
    uint32_t aH[2][2][4], bH[2][2][4], bL[2][2][4];

    for (int c = 0; c < 16; c++) {
        if (c < 15) asm volatile("cp.async.wait_group 1;" ::: "memory");
        else        asm volatile("cp.async.wait_group 0;" ::: "memory");
        __syncthreads();                     // publish stage c; fence reuse
        if (c + 2 < 16) issue_load(c + 2);

        const uint32_t buf = sb + (uint32_t)(c % 3) * STAGE_BYTES;

        // prime ks=0 fragments into buffer 0
#pragma unroll
        for (int mi = 0; mi < 2; mi++) ldm_x4(aH[0][mi], buf + offA[mi][0]);
#pragma unroll
        for (int pr = 0; pr < 2; pr++) {
            ldm_x4(bH[0][pr], buf + offB[pr][0]);
            ldm_x4(bL[0][pr], buf + (BL_OFF - BH_OFF) + offB[pr][0]);
        }

#pragma unroll
        for (int ks = 0; ks < 4; ks++) {
            const int cur = ks & 1;
            // prefetch next ks fragments before issuing this ks's MMAs
            if (ks < 3) {
                const int nxt = cur ^ 1;
#pragma unroll
                for (int mi = 0; mi < 2; mi++)
                    ldm_x4(aH[nxt][mi], buf + offA[mi][ks + 1]);
#pragma unroll
                for (int pr = 0; pr < 2; pr++) {
                    ldm_x4(bH[nxt][pr], buf + offB[pr][ks + 1]);
                    ldm_x4(bL[nxt][pr], buf + (BL_OFF - BH_OFF) + offB[pr][ks + 1]);
                }
            }
            // 2 products; (mi,ni) innermost so same-acc RAW distance is 8
#pragma unroll
            for (int mi = 0; mi < 2; mi++)
#pragma unroll
                for (int ni = 0; ni < 4; ni++)
                    mma_f32acc(acc[mi][ni], aH[cur][mi],
                               &bH[cur][ni >> 1][(ni & 1) * 2]);
#pragma unroll
            for (int mi = 0; mi < 2; mi++)
#pragma unroll
                for (int ni = 0; ni < 4; ni++)
                    mma_f32acc(acc[mi][ni], aH[cur][mi],
                               &bL[cur][ni >> 1][(ni & 1) * 2]);
        }
    }

    // ------------------------------- epilogue -------------------------------
    const int gpid = lid >> 2, tig = lid & 3;
    const float dt = 1.0f / 3.0f;
#pragma unroll
    for (int mi = 0; mi < 2; mi++) {
#pragma unroll
        for (int h2 = 0; h2 < 2; h2++) {
            const int row = rowBase + warpM * 32 + mi * 16 + gpid + h2 * 8;
#pragma unroll
            for (int ni = 0; ni < 4; ni++) {
                const int col = colBase + warpN * 32 + ni * 8 + tig * 2;
                const float c0 = acc[mi][ni][2 * h2];
                const float c1 = acc[mi][ni][2 * h2 + 1];
                const size_t base = (size_t)row * NS + col;
                if (mode == 0) {
                    float2 b2 = *(const float2*)(Xb + col);
                    *(float2*)(out_f + base) = make_float2(c0 + b2.x, c1 + b2.y);
                } else {
                    const float2 x2 = *(const float2*)(Xb + base);
                    const float2 hv = *(const float2*)(h_old + base);
                    const float2 a2 = *(const float2*)(Avec + col);
                    const float2 t2 = *(const float2*)(tauv + col);
                    float z0 = c0 + x2.x, z1 = c1 + x2.y;
                    float f0 = 1.0f / (1.0f + expf(-z0));
                    float f1 = 1.0f / (1.0f + expf(-z1));
                    float o0 = (hv.x + dt * f0 * a2.x) /
                               (1.0f + dt * (1.0f / t2.x + f0));
                    float o1 = (hv.y + dt * f1 * a2.y) /
                               (1.0f + dt * (1.0f / t2.y + f1));
                    *(float2*)(out_f + base) = make_float2(o0, o1);
                    *(__half2*)(out_hi + base) =
                        __halves2half2(__float2half(o0), __float2half(o1));
                }
            }
        }
    }
}

// ---------------------------------------------------------------------------
// Per-step halting (verified correct since R5)
// ---------------------------------------------------------------------------
__global__ __launch_bounds__(256) void halt_kernel(
    const float* __restrict__ h,
    const float* __restrict__ w_halt,
    const float* __restrict__ b_halt,
    float* __restrict__ tot_h)
{
    const int r = blockIdx.x;
    const int tid = threadIdx.x;
    const size_t base = (size_t)r * NS;

    float4 hv = *(const float4*)(h + base + tid * 4);
    float4 wv = *(const float4*)(w_halt + tid * 4);
    float s = hv.x * wv.x + hv.y * wv.y + hv.z * wv.z + hv.w * wv.w;
#pragma unroll
    for (int o = 16; o > 0; o >>= 1) s += __shfl_down_sync(0xffffffffu, s, o);

    __shared__ float red[8];
    __shared__ float wsh;
    if ((tid & 31) == 0) red[tid >> 5] = s;
    __syncthreads();
    if (tid == 0) {
        float tot = red[0] + red[1] + red[2] + red[3] +
                    red[4] + red[5] + red[6] + red[7];
        float sh = 1.0f / (1.0f + expf(-(tot + b_halt[0])));
        int ct = g_cont[r];
        float masked = ct ? sh : 0.0f;
        float ha = g_haltacc[r] + masked;
        bool ending = ct && (ha + sh > 0.99f);
        int ncont = (ct && !ending) ? 1 : 0;
        g_steps[r] += (float)ncont;
        g_haltacc[r] = ha;
        g_cont[r] = ncont;
        wsh = masked + (ending ? (1.0f - ha) : 0.0f);
    }
    __syncthreads();
    float w = wsh;
    if (w != 0.0f) {
        float4 t = *(float4*)(tot_h + base + tid * 4);
        t.x += w * hv.x; t.y += w * hv.y; t.z += w * hv.z; t.w += w * hv.w;
        *(float4*)(tot_h + base + tid * 4) = t;
    }
}

__global__ __launch_bounds__(256) void final_kernel(
    const float* __restrict__ h,
    float* __restrict__ tot_h,
    float* __restrict__ steps_out)
{
    const int r = blockIdx.x;
    const int tid = threadIdx.x;
    if (g_cont[r]) {
        const float w = 1.0f - g_haltacc[r];
        const size_t base = (size_t)r * NS;
        float4 hv = *(const float4*)(h + base + tid * 4);
        float4 t = *(float4*)(tot_h + base + tid * 4);
        t.x += w * hv.x; t.y += w * hv.y; t.z += w * hv.z; t.w += w * hv.w;
        *(float4*)(tot_h + base + tid * 4) = t;
    }
    if (tid == 0) steps_out[r] = g_steps[r] + 1.0f;
}

__global__ void ponder_kernel(float* __restrict__ outp) {
    const int tid = threadIdx.x;   // 1024 threads
    float v = g_haltacc[tid];
#pragma unroll
    for (int o = 16; o > 0; o >>= 1) v += __shfl_down_sync(0xffffffffu, v, o);
    __shared__ float sm[32];
    if ((tid & 31) == 0) sm[tid >> 5] = v;
    __syncthreads();
    if (tid < 32) {
        float x = sm[tid];
#pragma unroll
        for (int o = 16; o > 0; o >>= 1) x += __shfl_down_sync(0xffffffffu, x, o);
        if (tid == 0) outp[0] = -0.01f * (x * (1.0f / (float)NB));
    }
}

// ---------------------------------------------------------------------------
// Launch: out layout = [tot_h (B*S) | ponder (1) | tot_steps+1 (B)]
// ---------------------------------------------------------------------------
extern "C" void kernel_launch(void* const* d_in, const int* in_sizes, int n_in,
                              void* d_out, int out_size) {
    (void)in_sizes; (void)n_in; (void)out_size;
    const float* inputs  = (const float*)d_in[0];
    const float* hidden0 = (const float*)d_in[1];
    const float* Wx      = (const float*)d_in[2];
    const float* Wh      = (const float*)d_in[3];
    const float* bb      = (const float*)d_in[4];
    const float* Av      = (const float*)d_in[5];
    const float* tauv    = (const float*)d_in[6];
    const float* w_halt  = (const float*)d_in[7];
    const float* b_halt  = (const float*)d_in[8];
    float* out = (float*)d_out;

    float *X, *hf[2];
    __half *hhi[2], *WhTh, *WhTl, *WxTh, *WxTl, *inhi;
    cudaGetSymbolAddress((void**)&X,      g_X);
    cudaGetSymbolAddress((void**)&hf[0],  g_hf0);
    cudaGetSymbolAddress((void**)&hf[1],  g_hf1);
    cudaGetSymbolAddress((void**)&hhi[0], g_hhi0);
    cudaGetSymbolAddress((void**)&hhi[1], g_hhi1);
    cudaGetSymbolAddress((void**)&WhTh,   g_WhT_hi);
    cudaGetSymbolAddress((void**)&WhTl,   g_WhT_lo);
    cudaGetSymbolAddress((void**)&WxTh,   g_WxT_hi);
    cudaGetSymbolAddress((void**)&WxTl,   g_WxT_lo);
    cudaGetSymbolAddress((void**)&inhi,   g_inhi);

    cudaFuncSetAttribute(gemm_tc, cudaFuncAttributeMaxDynamicSharedMemorySize,
                         GEMM_SMEM);

    // exactly 3 prep launches (0,1,2)
    init_kernel<<<256, 256>>>(out);
    transpose_both<<<2048, 256>>>(Wx, Wh, WxTh, WxTl, WhTh, WhTl);
    cast_both<<<8192, 256>>>(inputs, hidden0, inhi, hhi[0]);

    dim3 grid(NS / 64, NB / 128);   // 16 x 8 = 128 CTAs = one wave

    // X = inputs @ Wx + b  (loop-invariant)     -> launch 3
    gemm_tc<<<grid, 256, GEMM_SMEM>>>(inhi, WxTh, WxTl, bb,
                                      nullptr, nullptr, nullptr,
                                      X, nullptr, 0);

    const float* hf_in = hidden0;
    int src = 0;
    for (int t = 0; t < NSTEPS; t++) {
        for (int u = 0; u < NUNF; u++) {
            int dst = src ^ 1;
            gemm_tc<<<grid, 256, GEMM_SMEM>>>(hhi[src], WhTh, WhTl,
                                              X, hf_in, Av, tauv,
                                              hf[dst], hhi[dst], 1);
            hf_in = hf[dst];
            src = dst;
        }
        halt_kernel<<<NB, 256>>>(hf_in, w_halt, b_halt, out);
    }

    final_kernel<<<NB, 256>>>(hf_in, out, out + (size_t)NB * NS + 1);
    ponder_kernel<<<1, 1024>>>(out + (size_t)NB * NS);
}

// round 16
// speedup vs baseline: 1.0204x; 1.0204x over previous
#include <cuda_runtime.h>
#include <cuda_fp16.h>
#include <math.h>
#include <stdint.h>

// Problem constants (B = D_IN = S = 1024)
#define NB 1024
#define NS 1024
#define NSTEPS 15   // TIME_LIMIT - 1
#define NUNF 3      // ODE_UNFOLDS

// ---------------------------------------------------------------------------
// Scratch (device globals; no allocations allowed)
// ---------------------------------------------------------------------------
__device__ __align__(16) float g_X  [NB * NS];     // inputs @ Wx + b
__device__ __align__(16) float g_hf0[NB * NS];     // fp32 hidden ping-pong
__device__ __align__(16) float g_hf1[NB * NS];
__device__ __align__(16) __half g_hhi0[NB * NS];   // fp16 hidden ping-pong
__device__ __align__(16) __half g_hhi1[NB * NS];
__device__ __align__(16) __half g_WhT_hi[NS * NS];   // Wh^T split
__device__ __align__(16) __half g_WhT_lo[NS * NS];
__device__ __align__(16) __half g_WxT_hi[NS * NS];   // Wx^T split
__device__ __align__(16) __half g_WxT_lo[NS * NS];
__device__ __align__(16) __half g_inhi[NB * NS];     // inputs (fp16)
__device__ float g_haltacc[NB];   // halt_acc == tot_rem
__device__ float g_steps[NB];
__device__ int   g_cont[NB];

// ---------------------------------------------------------------------------
// Warp-level tensor-core helpers (sm_80+ PTX; assembles for plain sm_100)
// ---------------------------------------------------------------------------
__device__ __forceinline__ uint32_t smem_u32(const void* p) {
    uint32_t a;
    asm("{ .reg .u64 t; cvta.to.shared.u64 t, %1; cvt.u32.u64 %0, t; }"
        : "=r"(a) : "l"(p));
    return a;
}

__device__ __forceinline__ void ldm_x4(uint32_t* r, uint32_t addr) {
    asm volatile("ldmatrix.sync.aligned.m8n8.x4.shared.b16 {%0,%1,%2,%3}, [%4];"
        : "=r"(r[0]), "=r"(r[1]), "=r"(r[2]), "=r"(r[3]) : "r"(addr));
}
// fp16 operands, fp32 accumulate
__device__ __forceinline__ void mma_f32acc(float* c, const uint32_t* a,
                                           const uint32_t* b) {
    asm volatile(
        "mma.sync.aligned.m16n8k16.row.col.f32.f16.f16.f32 "
        "{%0,%1,%2,%3}, {%4,%5,%6,%7}, {%8,%9}, {%0,%1,%2,%3};"
        : "+f"(c[0]), "+f"(c[1]), "+f"(c[2]), "+f"(c[3])
        : "r"(a[0]), "r"(a[1]), "r"(a[2]), "r"(a[3]), "r"(b[0]), "r"(b[1]));
}
__device__ __forceinline__ void cp16(uint32_t saddr, const void* g) {
    asm volatile("cp.async.cg.shared.global [%0], [%1], 16;"
                 :: "r"(saddr), "l"(g));
}

// ---------------------------------------------------------------------------
// Prep kernels (exactly 3 launches so gemm_tc lands in the ncu window)
// ---------------------------------------------------------------------------
__global__ __launch_bounds__(256) void init_kernel(float* __restrict__ tot_h) {
    int i = blockIdx.x * blockDim.x + threadIdx.x;
    int stride = gridDim.x * blockDim.x;
    for (int j = i; j < NB * NS; j += stride) tot_h[j] = 0.0f;
    if (i < NB) { g_haltacc[i] = 0.0f; g_steps[i] = 0.0f; g_cont[i] = 1; }
}

// Both weight transposes in one launch: blocks 0-1023 Wx, 1024-2047 Wh.
__global__ __launch_bounds__(256) void transpose_both(
    const float* __restrict__ Wx, const float* __restrict__ Wh,
    __half* __restrict__ WxThi, __half* __restrict__ WxTlo,
    __half* __restrict__ WhThi, __half* __restrict__ WhTlo)
{
    const int which = blockIdx.x >> 10;
    const int t = blockIdx.x & 1023;
    const float* W = which ? Wh : Wx;
    __half* Thi = which ? WhThi : WxThi;
    __half* Tlo = which ? WhTlo : WxTlo;

    __shared__ float tb[32][33];
    const int x  = threadIdx.x & 31;
    const int y0 = threadIdx.x >> 5;    // 0..7
    const int bk = (t >> 5) * 32;       // W row (k) block
    const int bn = (t & 31) * 32;       // W col (n) block
#pragma unroll
    for (int i = 0; i < 32; i += 8)
        tb[y0 + i][x] = W[(size_t)(bk + y0 + i) * NS + bn + x];
    __syncthreads();
#pragma unroll
    for (int i = 0; i < 32; i += 8) {
        float v = tb[x][y0 + i];  // = W[bk+x][bn+y0+i]
        size_t o = (size_t)(bn + y0 + i) * NS + bk + x;
        __half h = __float2half(v);
        Thi[o] = h;
        Tlo[o] = __float2half(v - __half2float(h));
    }
}

// Both fp16 casts in one launch: blocks 0-4095 inputs, 4096-8191 hidden0.
__global__ __launch_bounds__(256) void cast_both(
    const float* __restrict__ inputs, const float* __restrict__ hidden0,
    __half* __restrict__ ihi, __half* __restrict__ hhi)
{
    const int which = blockIdx.x >> 12;
    const int i = ((blockIdx.x & 4095) << 8) + threadIdx.x;
    const float* src = which ? hidden0 : inputs;
    __half* hi = which ? hhi : ihi;
    hi[i] = __float2half(src[i]);
}

// ---------------------------------------------------------------------------
// Tensor-core GEMM (2-product fp16) + fused LTC epilogue.
//   C = Ah.Bh + Ah.Bl   (fp32 acc; dropped A_lo.B ~ 1.2e-4 on z)
// CTA tile 64(m) x 64(n), 4 warps of 32x32 (LDSM 0.375 x4-ops/MMA),
// 128 threads, grid 256 CTAs -> TWO CTAs per SM for bubble overlap.
// K-chunks of 64, 3-stage cp.async pipeline, ONE __syncthreads per chunk,
// XOR-swizzled smem, frag double-buffer across ks.
//   mode 0: out_f = C + bias[col]
//   mode 1: z = C + X; f = sigmoid(z);
//           h' = (h_old + dt f A)/(1 + dt(1/tau + f))
//           out_f = h' fp32; out_hi = fp16(h')
// ---------------------------------------------------------------------------
#define AH_OFF 0
#define BH_OFF 8192
#define BL_OFF 16384
#define STAGE_BYTES 24576
#define GEMM_SMEM (3 * STAGE_BYTES)   // 73728 -> 2 CTAs/SM (147456 < 228K)

__global__ __launch_bounds__(128, 2) void gemm_tc(
    const __half* __restrict__ Ahi,
    const __half* __restrict__ Bhi, const __half* __restrict__ Blo,
    const float* __restrict__ Xb,      // mode0: bias[S]; mode1: X [B x S]
    const float* __restrict__ h_old,   // mode1
    const float* __restrict__ Avec, const float* __restrict__ tauv,
    float* __restrict__ out_f,
    __half* __restrict__ out_hi,
    int mode)
{
    extern __shared__ char smem[];
    const uint32_t sb = smem_u32(smem);

    const int tid = threadIdx.x;
    const int wid = tid >> 5, lid = tid & 31;
    const int warpM = wid >> 1;       // 0..1 -> m32 tile
    const int warpN = wid & 1;        // 0..1 -> n32 tile
    const int rowBase = blockIdx.y * 64;
    const int colBase = blockIdx.x * 64;

    // ldmatrix offsets (stage-relative).
    const int laneAr = lid & 15, laneAk = lid >> 4;
    uint32_t offA[2][4], offB[2][4];
#pragma unroll
    for (int mi = 0; mi < 2; mi++) {
        const int rowA = warpM * 32 + mi * 16 + laneAr;
#pragma unroll
        for (int ks = 0; ks < 4; ks++)
            offA[mi][ks] = (uint32_t)(AH_OFF + rowA * 128 +
                ((ks * 32 + laneAk * 16) ^ ((rowA & 7) << 4)));
    }
    const int laneBt = lid >> 3;      // tile id 0..3
#pragma unroll
    for (int pr = 0; pr < 2; pr++) {
        const int rowB = warpN * 32 + pr * 16 + (laneBt >> 1) * 8 + (lid & 7);
#pragma unroll
        for (int ks = 0; ks < 4; ks++)
            offB[pr][ks] = (uint32_t)(BH_OFF + rowB * 128 +
                ((ks * 32 + (laneBt & 1) * 16) ^ ((rowB & 7) << 4)));
    }

    float acc[2][4][4];
#pragma unroll
    for (int mi = 0; mi < 2; mi++)
#pragma unroll
        for (int ni = 0; ni < 4; ni++)
#pragma unroll
            for (int j = 0; j < 4; j++) acc[mi][ni][j] = 0.0f;

    const char* ahg = (const char*)Ahi + (size_t)rowBase * 2048;
    const char* bhg = (const char*)Bhi + (size_t)colBase * 2048;
    const char* blg = (const char*)Blo + (size_t)colBase * 2048;

    auto issue_load = [&](int cc) {
        const int kb = cc * 128;      // byte offset along K
        const uint32_t buf = sb + (uint32_t)(cc % 3) * STAGE_BYTES;
#pragma unroll
        for (int i = 0; i < 4; i++) {            // A: 64 rows x 8 segs = 512
            int idx = i * 128 + tid;
            int row = idx >> 3, s = idx & 7;
            uint32_t off = (uint32_t)(row * 128 + ((s * 16) ^ ((row & 7) << 4)));
            cp16(buf + AH_OFF + off, ahg + (size_t)row * 2048 + kb + s * 16);
        }
#pragma unroll
        for (int i = 0; i < 4; i++) {            // B: 64 rows x 8 segs, hi+lo
            int idx = i * 128 + tid;
            int row = idx >> 3, s = idx & 7;
            uint32_t off = (uint32_t)(row * 128 + ((s * 16) ^ ((row & 7) << 4)));
            const size_t g = (size_t)row * 2048 + kb + s * 16;
            cp16(buf + BH_OFF + off, bhg + g);
            cp16(buf + BL_OFF + off, blg + g);
        }
        asm volatile("cp.async.commit_group;" ::: "memory");
    };

    issue_load(0);
    issue_load(1);

    // double-buffered fragments, pipelined across ks
    uint32_t aH[2][2][4], bH[2][2][4], bL[2][2][4];

    for (int c = 0; c < 16; c++) {
        if (c < 15) asm volatile("cp.async.wait_group 1;" ::: "memory");
        else        asm volatile("cp.async.wait_group 0;" ::: "memory");
        __syncthreads();                     // publish stage c; fence reuse
        if (c + 2 < 16) issue_load(c + 2);

        const uint32_t buf = sb + (uint32_t)(c % 3) * STAGE_BYTES;

        // prime ks=0 fragments into buffer 0
#pragma unroll
        for (int mi = 0; mi < 2; mi++) ldm_x4(aH[0][mi], buf + offA[mi][0]);
#pragma unroll
        for (int pr = 0; pr < 2; pr++) {
            ldm_x4(bH[0][pr], buf + offB[pr][0]);
            ldm_x4(bL[0][pr], buf + (BL_OFF - BH_OFF) + offB[pr][0]);
        }

#pragma unroll
        for (int ks = 0; ks < 4; ks++) {
            const int cur = ks & 1;
            // prefetch next ks fragments before issuing this ks's MMAs
            if (ks < 3) {
                const int nxt = cur ^ 1;
#pragma unroll
                for (int mi = 0; mi < 2; mi++)
                    ldm_x4(aH[nxt][mi], buf + offA[mi][ks + 1]);
#pragma unroll
                for (int pr = 0; pr < 2; pr++) {
                    ldm_x4(bH[nxt][pr], buf + offB[pr][ks + 1]);
                    ldm_x4(bL[nxt][pr], buf + (BL_OFF - BH_OFF) + offB[pr][ks + 1]);
                }
            }
            // 2 products; (mi,ni) innermost so same-acc RAW distance is 8
#pragma unroll
            for (int mi = 0; mi < 2; mi++)
#pragma unroll
                for (int ni = 0; ni < 4; ni++)
                    mma_f32acc(acc[mi][ni], aH[cur][mi],
                               &bH[cur][ni >> 1][(ni & 1) * 2]);
#pragma unroll
            for (int mi = 0; mi < 2; mi++)
#pragma unroll
                for (int ni = 0; ni < 4; ni++)
                    mma_f32acc(acc[mi][ni], aH[cur][mi],
                               &bL[cur][ni >> 1][(ni & 1) * 2]);
        }
    }

    // ------------------------------- epilogue -------------------------------
    const int gpid = lid >> 2, tig = lid & 3;
    const float dt = 1.0f / 3.0f;
#pragma unroll
    for (int mi = 0; mi < 2; mi++) {
#pragma unroll
        for (int h2 = 0; h2 < 2; h2++) {
            const int row = rowBase + warpM * 32 + mi * 16 + gpid + h2 * 8;
#pragma unroll
            for (int ni = 0; ni < 4; ni++) {
                const int col = colBase + warpN * 32 + ni * 8 + tig * 2;
                const float c0 = acc[mi][ni][2 * h2];
                const float c1 = acc[mi][ni][2 * h2 + 1];
                const size_t base = (size_t)row * NS + col;
                if (mode == 0) {
                    float2 b2 = *(const float2*)(Xb + col);
                    *(float2*)(out_f + base) = make_float2(c0 + b2.x, c1 + b2.y);
                } else {
                    const float2 x2 = *(const float2*)(Xb + base);
                    const float2 hv = *(const float2*)(h_old + base);
                    const float2 a2 = *(const float2*)(Avec + col);
                    const float2 t2 = *(const float2*)(tauv + col);
                    float z0 = c0 + x2.x, z1 = c1 + x2.y;
                    float f0 = 1.0f / (1.0f + expf(-z0));
                    float f1 = 1.0f / (1.0f + expf(-z1));
                    float o0 = (hv.x + dt * f0 * a2.x) /
                               (1.0f + dt * (1.0f / t2.x + f0));
                    float o1 = (hv.y + dt * f1 * a2.y) /
                               (1.0f + dt * (1.0f / t2.y + f1));
                    *(float2*)(out_f + base) = make_float2(o0, o1);
                    *(__half2*)(out_hi + base) =
                        __halves2half2(__float2half(o0), __float2half(o1));
                }
            }
        }
    }
}

// ---------------------------------------------------------------------------
// Per-step halting (verified correct since R5)
// ---------------------------------------------------------------------------
__global__ __launch_bounds__(256) void halt_kernel(
    const float* __restrict__ h,
    const float* __restrict__ w_halt,
    const float* __restrict__ b_halt,
    float* __restrict__ tot_h)
{
    const int r = blockIdx.x;
    const int tid = threadIdx.x;
    const size_t base = (size_t)r * NS;

    float4 hv = *(const float4*)(h + base + tid * 4);
    float4 wv = *(const float4*)(w_halt + tid * 4);
    float s = hv.x * wv.x + hv.y * wv.y + hv.z * wv.z + hv.w * wv.w;
#pragma unroll
    for (int o = 16; o > 0; o >>= 1) s += __shfl_down_sync(0xffffffffu, s, o);

    __shared__ float red[8];
    __shared__ float wsh;
    if ((tid & 31) == 0) red[tid >> 5] = s;
    __syncthreads();
    if (tid == 0) {
        float tot = red[0] + red[1] + red[2] + red[3] +
                    red[4] + red[5] + red[6] + red[7];
        float sh = 1.0f / (1.0f + expf(-(tot + b_halt[0])));
        int ct = g_cont[r];
        float masked = ct ? sh : 0.0f;
        float ha = g_haltacc[r] + masked;
        bool ending = ct && (ha + sh > 0.99f);
        int ncont = (ct && !ending) ? 1 : 0;
        g_steps[r] += (float)ncont;
        g_haltacc[r] = ha;
        g_cont[r] = ncont;
        wsh = masked + (ending ? (1.0f - ha) : 0.0f);
    }
    __syncthreads();
    float w = wsh;
    if (w != 0.0f) {
        float4 t = *(float4*)(tot_h + base + tid * 4);
        t.x += w * hv.x; t.y += w * hv.y; t.z += w * hv.z; t.w += w * hv.w;
        *(float4*)(tot_h + base + tid * 4) = t;
    }
}

__global__ __launch_bounds__(256) void final_kernel(
    const float* __restrict__ h,
    float* __restrict__ tot_h,
    float* __restrict__ steps_out)
{
    const int r = blockIdx.x;
    const int tid = threadIdx.x;
    if (g_cont[r]) {
        const float w = 1.0f - g_haltacc[r];
        const size_t base = (size_t)r * NS;
        float4 hv = *(const float4*)(h + base + tid * 4);
        float4 t = *(float4*)(tot_h + base + tid * 4);
        t.x += w * hv.x; t.y += w * hv.y; t.z += w * hv.z; t.w += w * hv.w;
        *(float4*)(tot_h + base + tid * 4) = t;
    }
    if (tid == 0) steps_out[r] = g_steps[r] + 1.0f;
}

__global__ void ponder_kernel(float* __restrict__ outp) {
    const int tid = threadIdx.x;   // 1024 threads
    float v = g_haltacc[tid];
#pragma unroll
    for (int o = 16; o > 0; o >>= 1) v += __shfl_down_sync(0xffffffffu, v, o);
    __shared__ float sm[32];
    if ((tid & 31) == 0) sm[tid >> 5] = v;
    __syncthreads();
    if (tid < 32) {
        float x = sm[tid];
#pragma unroll
        for (int o = 16; o > 0; o >>= 1) x += __shfl_down_sync(0xffffffffu, x, o);
        if (tid == 0) outp[0] = -0.01f * (x * (1.0f / (float)NB));
    }
}

// ---------------------------------------------------------------------------
// Launch: out layout = [tot_h (B*S) | ponder (1) | tot_steps+1 (B)]
// ---------------------------------------------------------------------------
extern "C" void kernel_launch(void* const* d_in, const int* in_sizes, int n_in,
                              void* d_out, int out_size) {
    (void)in_sizes; (void)n_in; (void)out_size;
    const float* inputs  = (const float*)d_in[0];
    const float* hidden0 = (const float*)d_in[1];
    const float* Wx      = (const float*)d_in[2];
    const float* Wh      = (const float*)d_in[3];
    const float* bb      = (const float*)d_in[4];
    const float* Av      = (const float*)d_in[5];
    const float* tauv    = (const float*)d_in[6];
    const float* w_halt  = (const float*)d_in[7];
    const float* b_halt  = (const float*)d_in[8];
    float* out = (float*)d_out;

    float *X, *hf[2];
    __half *hhi[2], *WhTh, *WhTl, *WxTh, *WxTl, *inhi;
    cudaGetSymbolAddress((void**)&X,      g_X);
    cudaGetSymbolAddress((void**)&hf[0],  g_hf0);
    cudaGetSymbolAddress((void**)&hf[1],  g_hf1);
    cudaGetSymbolAddress((void**)&hhi[0], g_hhi0);
    cudaGetSymbolAddress((void**)&hhi[1], g_hhi1);
    cudaGetSymbolAddress((void**)&WhTh,   g_WhT_hi);
    cudaGetSymbolAddress((void**)&WhTl,   g_WhT_lo);
    cudaGetSymbolAddress((void**)&WxTh,   g_WxT_hi);
    cudaGetSymbolAddress((void**)&WxTl,   g_WxT_lo);
    cudaGetSymbolAddress((void**)&inhi,   g_inhi);

    cudaFuncSetAttribute(gemm_tc, cudaFuncAttributeMaxDynamicSharedMemorySize,
                         GEMM_SMEM);

    // exactly 3 prep launches (0,1,2)
    init_kernel<<<256, 256>>>(out);
    transpose_both<<<2048, 256>>>(Wx, Wh, WxTh, WxTl, WhTh, WhTl);
    cast_both<<<8192, 256>>>(inputs, hidden0, inhi, hhi[0]);

    dim3 grid(NS / 64, NB / 64);   // 16 x 16 = 256 CTAs -> 2 per SM

    // X = inputs @ Wx + b  (loop-invariant)     -> launch 3
    gemm_tc<<<grid, 128, GEMM_SMEM>>>(inhi, WxTh, WxTl, bb,
                                      nullptr, nullptr, nullptr,
                                      X, nullptr, 0);

    const float* hf_in = hidden0;
    int src = 0;
    for (int t = 0; t < NSTEPS; t++) {
        for (int u = 0; u < NUNF; u++) {
            int dst = src ^ 1;
            gemm_tc<<<grid, 128, GEMM_SMEM>>>(hhi[src], WhTh, WhTl,
                                              X, hf_in, Av, tauv,
                                              hf[dst], hhi[dst], 1);
            hf_in = hf[dst];
            src = dst;
        }
        halt_kernel<<<NB, 256>>>(hf_in, w_halt, b_halt, out);
    }

    final_kernel<<<NB, 256>>>(hf_in, out, out + (size_t)NB * NS + 1);
    ponder_kernel<<<1, 1024>>>(out + (size_t)NB * NS);
}